// round 1
// baseline (speedup 1.0000x reference)
#include <cuda_runtime.h>
#include <cuda_bf16.h>
#include <cstdint>

// Problem constants
#define NROWS 8192
#define DDIM  768

// GEMM tiling
#define BM 64
#define BN 128
#define BK 32
#define KPAD 40          // +8 bf16 padding -> 80B row stride (conflict-free ldmatrix)
#define NKC (DDIM / BK)  // 24 k-chunks
#define NNT (NROWS / BN) // 64 n-tiles

// Normalized bf16 copies (device scratch; no allocations allowed)
__device__ __nv_bfloat16 g_exn[NROWS * DDIM];
__device__ __nv_bfloat16 g_eyn[NROWS * DDIM];

// ---------------------------------------------------------------------------
// Row L2-normalize fp32 -> bf16 (matches ref: norm = max(||x||, 1e-8))
// ---------------------------------------------------------------------------
__global__ void normalize_kernel(const float* __restrict__ in, int sel) {
    __nv_bfloat16* out = sel ? g_eyn : g_exn;
    const int row = blockIdx.x;
    const int tid = threadIdx.x;
    const float* p = in + (size_t)row * DDIM;

    float v[3];
    float s = 0.f;
#pragma unroll
    for (int i = 0; i < 3; i++) {
        v[i] = p[tid + i * 256];
        s += v[i] * v[i];
    }
#pragma unroll
    for (int o = 16; o; o >>= 1) s += __shfl_xor_sync(0xffffffffu, s, o);

    __shared__ float wsum[8];
    __shared__ float sinv;
    if ((tid & 31) == 0) wsum[tid >> 5] = s;
    __syncthreads();
    if (tid == 0) {
        float t = 0.f;
#pragma unroll
        for (int i = 0; i < 8; i++) t += wsum[i];
        float nrm = fmaxf(sqrtf(t), 1e-8f);
        sinv = 1.0f / nrm;
    }
    __syncthreads();
    const float inv = sinv;
    __nv_bfloat16* q = out + (size_t)row * DDIM;
#pragma unroll
    for (int i = 0; i < 3; i++)
        q[tid + i * 256] = __float2bfloat16(v[i] * inv);
}

// ---------------------------------------------------------------------------
// PTX helpers
// ---------------------------------------------------------------------------
__device__ __forceinline__ void cpa16(uint32_t dst, const void* src) {
    asm volatile("cp.async.cg.shared.global [%0], [%1], 16;" :: "r"(dst), "l"(src));
}
__device__ __forceinline__ void cpa_commit() {
    asm volatile("cp.async.commit_group;");
}
__device__ __forceinline__ void cpa_wait_all() {
    asm volatile("cp.async.wait_group 0;");
}
__device__ __forceinline__ void ldsm4(uint32_t (&r)[4], uint32_t addr) {
    asm volatile("ldmatrix.sync.aligned.m8n8.x4.shared.b16 {%0,%1,%2,%3}, [%4];"
                 : "=r"(r[0]), "=r"(r[1]), "=r"(r[2]), "=r"(r[3]) : "r"(addr));
}
__device__ __forceinline__ void ldsm2(uint32_t (&r)[2], uint32_t addr) {
    asm volatile("ldmatrix.sync.aligned.m8n8.x2.shared.b16 {%0,%1}, [%2];"
                 : "=r"(r[0]), "=r"(r[1]) : "r"(addr));
}
__device__ __forceinline__ void mma16816(float (&c)[4], const uint32_t (&a)[4],
                                         const uint32_t (&b)[2]) {
    asm volatile(
        "mma.sync.aligned.m16n8k16.row.col.f32.bf16.bf16.f32 "
        "{%0,%1,%2,%3}, {%4,%5,%6,%7}, {%8,%9}, {%0,%1,%2,%3};"
        : "+f"(c[0]), "+f"(c[1]), "+f"(c[2]), "+f"(c[3])
        : "r"(a[0]), "r"(a[1]), "r"(a[2]), "r"(a[3]), "r"(b[0]), "r"(b[1]));
}

// ---------------------------------------------------------------------------
// Fused GEMM (exn @ eyn^T) + row-max.
// Grid: NROWS/BM = 128 CTAs; each CTA owns BM ex-rows, loops over all ey tiles.
// ---------------------------------------------------------------------------
__global__ __launch_bounds__(256, 1) void chamfer_kernel(float* __restrict__ out) {
    __shared__ __nv_bfloat16 As[2][BM][KPAD];
    __shared__ __nv_bfloat16 Bs[2][BN][KPAD];
    __shared__ float red[4][BM];

    const int tid = threadIdx.x;
    const int lane = tid & 31;
    const int wid = tid >> 5;
    const int wm = wid >> 2;   // 0..1  (M warp)
    const int wn = wid & 3;    // 0..3  (N warp)
    const int g = lane >> 2;   // group id (row within 8)
    const int tig = lane & 3;  // thread in group

    const int bm = blockIdx.x;
    const __nv_bfloat16* Ag = g_exn + (size_t)bm * BM * DDIM;

    // cp.async task decomposition
    const int a_row = tid >> 2;     // 0..63
    const int a_chunk = tid & 3;    // 0..3 (x8 bf16 = 16B)
    const int b_row0 = tid >> 2;    // 0..63
    const int b_row1 = 64 + b_row0; // 64..127
    const int b_chunk = tid & 3;

    uint32_t aDst[2], bDst0[2], bDst1[2];
#pragma unroll
    for (int s = 0; s < 2; s++) {
        aDst[s]  = (uint32_t)__cvta_generic_to_shared(&As[s][a_row][a_chunk * 8]);
        bDst0[s] = (uint32_t)__cvta_generic_to_shared(&Bs[s][b_row0][b_chunk * 8]);
        bDst1[s] = (uint32_t)__cvta_generic_to_shared(&Bs[s][b_row1][b_chunk * 8]);
    }

    // ldmatrix shared addresses (per kk-half recomputed via offset)
    const int a_lrow = lane & 15;          // row within 16
    const int a_koff = (lane >> 4) * 8;    // k-half within ldmatrix
    const int b_lrow = lane & 7;
    const int b_koff = ((lane >> 3) & 1) * 8;

    float runmax[2][2];
#pragma unroll
    for (int i = 0; i < 2; i++)
#pragma unroll
        for (int j = 0; j < 2; j++) runmax[i][j] = -1e30f;

    for (int nt = 0; nt < NNT; ++nt) {
        const __nv_bfloat16* Bgn = g_eyn + (size_t)nt * BN * DDIM;

        float acc[2][4][4];
#pragma unroll
        for (int mt = 0; mt < 2; mt++)
#pragma unroll
            for (int n4 = 0; n4 < 4; n4++)
#pragma unroll
                for (int r = 0; r < 4; r++) acc[mt][n4][r] = 0.f;

        // preload k-chunk 0 into stage 0
        cpa16(aDst[0],  Ag  + a_row  * DDIM + a_chunk * 8);
        cpa16(bDst0[0], Bgn + b_row0 * DDIM + b_chunk * 8);
        cpa16(bDst1[0], Bgn + b_row1 * DDIM + b_chunk * 8);
        cpa_commit();

        for (int kt = 0; kt < NKC; ++kt) {
            cpa_wait_all();
            __syncthreads();

            if (kt + 1 < NKC) {
                const int k0 = (kt + 1) * BK;
                const int s = (kt + 1) & 1;
                cpa16(aDst[s],  Ag  + a_row  * DDIM + k0 + a_chunk * 8);
                cpa16(bDst0[s], Bgn + b_row0 * DDIM + k0 + b_chunk * 8);
                cpa16(bDst1[s], Bgn + b_row1 * DDIM + k0 + b_chunk * 8);
                cpa_commit();
            }

            const int s = kt & 1;
#pragma unroll
            for (int kk = 0; kk < 2; ++kk) {
                uint32_t a[2][4];
                uint32_t b[4][2];
#pragma unroll
                for (int mt = 0; mt < 2; mt++) {
                    uint32_t addr = (uint32_t)__cvta_generic_to_shared(
                        &As[s][wm * 32 + mt * 16 + a_lrow][kk * 16 + a_koff]);
                    ldsm4(a[mt], addr);
                }
#pragma unroll
                for (int n4 = 0; n4 < 4; n4++) {
                    uint32_t addr = (uint32_t)__cvta_generic_to_shared(
                        &Bs[s][wn * 32 + n4 * 8 + b_lrow][kk * 16 + b_koff]);
                    ldsm2(b[n4], addr);
                }
#pragma unroll
                for (int mt = 0; mt < 2; mt++)
#pragma unroll
                    for (int n4 = 0; n4 < 4; n4++)
                        mma16816(acc[mt][n4], a[mt], b[n4]);
            }
        }

        // fold this n-tile into running row maxes
#pragma unroll
        for (int mt = 0; mt < 2; mt++) {
            float m0 = runmax[mt][0], m1 = runmax[mt][1];
#pragma unroll
            for (int n4 = 0; n4 < 4; n4++) {
                m0 = fmaxf(m0, fmaxf(acc[mt][n4][0], acc[mt][n4][1]));
                m1 = fmaxf(m1, fmaxf(acc[mt][n4][2], acc[mt][n4][3]));
            }
            runmax[mt][0] = m0;
            runmax[mt][1] = m1;
        }
    }

    // cross-thread reduction: lanes in the same row group are consecutive (g*4 + tig)
#pragma unroll
    for (int mt = 0; mt < 2; mt++) {
#pragma unroll
        for (int h = 0; h < 2; h++) {
            float m = runmax[mt][h];
            m = fmaxf(m, __shfl_xor_sync(0xffffffffu, m, 1));
            m = fmaxf(m, __shfl_xor_sync(0xffffffffu, m, 2));
            if (tig == 0)
                red[wn][wm * 32 + mt * 16 + h * 8 + g] = m;
        }
    }
    __syncthreads();

    if (tid < BM) {
        float m = red[0][tid];
#pragma unroll
        for (int w = 1; w < 4; w++) m = fmaxf(m, red[w][tid]);
        out[bm * BM + tid] = m;
    }
}

// ---------------------------------------------------------------------------
// Launch
// ---------------------------------------------------------------------------
extern "C" void kernel_launch(void* const* d_in, const int* in_sizes, int n_in,
                              void* d_out, int out_size) {
    const float* ex = (const float*)d_in[0];
    const float* ey = (const float*)d_in[1];
    float* out = (float*)d_out;

    normalize_kernel<<<NROWS, 256>>>(ex, 0);
    normalize_kernel<<<NROWS, 256>>>(ey, 1);
    chamfer_kernel<<<NROWS / BM, 256>>>(out);
}

// round 3
// speedup vs baseline: 1.4351x; 1.4351x over previous
#include <cuda_runtime.h>
#include <cuda_bf16.h>
#include <cstdint>

// ---------------- problem constants ----------------
#define NROWS 8192
#define DDIM  768

// ---------------- GEMM tiling ----------------
#define BM 64             // ex rows per CTA (A resident in smem)
#define BN 256            // ey rows per B tile
#define BK 32             // k per pipeline chunk
#define NKT (DDIM / BK)   // 24 k-chunks per n-tile
#define NNT (NROWS / BN)  // 32 n-tiles
#define TOTAL_CH (NNT * NKT)  // 768

// smem layout
#define A_STRIDE_B 1552               // (768+8) bf16 per row -> conflict-free ldsm
#define OFF_A 0
#define A_BYTES (BM * A_STRIDE_B)     // 99328
#define B_ROW_B 80                    // (32+8) bf16 per row
#define B_STAGE_B (BN * B_ROW_B)      // 20480
#define OFF_B A_BYTES
#define OFF_RED (OFF_B + 3 * B_STAGE_B)   // 160768
#define SMEM_TOTAL (OFF_RED + 4 * BM * 4) // + red[4][64] floats

// ---------------- device scratch ----------------
__device__ __nv_bfloat16 g_exn[NROWS * DDIM];
__device__ __nv_bfloat16 g_eyn[NROWS * DDIM];

// ---------------- PTX helpers ----------------
__device__ __forceinline__ uint32_t s2u(const void* p) {
    uint32_t a;
    asm("{ .reg .u64 t; cvta.to.shared.u64 t, %1; cvt.u32.u64 %0, t; }" : "=r"(a) : "l"(p));
    return a;
}
__device__ __forceinline__ void cpa16(uint32_t dst, const void* src) {
    asm volatile("cp.async.cg.shared.global [%0], [%1], 16;" :: "r"(dst), "l"(src));
}
__device__ __forceinline__ void cpa_commit() { asm volatile("cp.async.commit_group;"); }
__device__ __forceinline__ void cpa_wait1()  { asm volatile("cp.async.wait_group 1;"); }
__device__ __forceinline__ void ldsm4(uint32_t (&r)[4], uint32_t addr) {
    asm volatile("ldmatrix.sync.aligned.m8n8.x4.shared.b16 {%0,%1,%2,%3}, [%4];"
                 : "=r"(r[0]), "=r"(r[1]), "=r"(r[2]), "=r"(r[3]) : "r"(addr));
}
__device__ __forceinline__ void mma16816(float (&c)[4], const uint32_t (&a)[4],
                                         uint32_t b0, uint32_t b1) {
    asm volatile(
        "mma.sync.aligned.m16n8k16.row.col.f32.bf16.bf16.f32 "
        "{%0,%1,%2,%3}, {%4,%5,%6,%7}, {%8,%9}, {%0,%1,%2,%3};"
        : "+f"(c[0]), "+f"(c[1]), "+f"(c[2]), "+f"(c[3])
        : "r"(a[0]), "r"(a[1]), "r"(a[2]), "r"(a[3]), "r"(b0), "r"(b1));
}

// ---------------------------------------------------------------------------
// Row L2-normalize fp32 -> bf16 (ref: norm = max(||x||, 1e-8))
// ---------------------------------------------------------------------------
__global__ void normalize_kernel(const float* __restrict__ in, int sel) {
    __nv_bfloat16* out = sel ? g_eyn : g_exn;
    const int row = blockIdx.x;
    const int tid = threadIdx.x;
    const float* p = in + (size_t)row * DDIM;

    float v[3];
    float s = 0.f;
#pragma unroll
    for (int i = 0; i < 3; i++) { v[i] = p[tid + i * 256]; s += v[i] * v[i]; }
#pragma unroll
    for (int o = 16; o; o >>= 1) s += __shfl_xor_sync(0xffffffffu, s, o);

    __shared__ float wsum[8];
    __shared__ float sinv;
    if ((tid & 31) == 0) wsum[tid >> 5] = s;
    __syncthreads();
    if (tid == 0) {
        float t = 0.f;
#pragma unroll
        for (int i = 0; i < 8; i++) t += wsum[i];
        sinv = 1.0f / fmaxf(sqrtf(t), 1e-8f);
    }
    __syncthreads();
    const float inv = sinv;
    __nv_bfloat16* q = out + (size_t)row * DDIM;
#pragma unroll
    for (int i = 0; i < 3; i++) q[tid + i * 256] = __float2bfloat16(v[i] * inv);
}

// ---------------------------------------------------------------------------
// Fused GEMM (exn @ eyn^T) + row-max. HMMA path, A resident, 3-stage B ring.
// grid = 128 CTAs; warp grid 2x4 (wm,wn); warp tile 32x64.
// ---------------------------------------------------------------------------
__global__ __launch_bounds__(256, 1) void chamfer_kernel(float* __restrict__ out) {
    extern __shared__ char smem[];
    const uint32_t sb = s2u(smem);
    float* red = (float*)(smem + OFF_RED);

    const int tid = threadIdx.x;
    const int lane = tid & 31;
    const int wid = tid >> 5;
    const int wm = wid >> 2;   // 0..1
    const int wn = wid & 3;    // 0..3
    const int g = lane >> 2;
    const int tig = lane & 3;

    const int bm = blockIdx.x;
    const __nv_bfloat16* Ag = g_exn + (size_t)bm * BM * DDIM;

    // ---- resident A load: 64 rows x 96 16B-chunks ----
    for (int idx = tid; idx < BM * 96; idx += 256) {
        const int row = idx / 96, c = idx % 96;
        cpa16(sb + OFF_A + row * A_STRIDE_B + c * 16, Ag + row * DDIM + c * 8);
    }
    cpa_commit();

    // B stage loader: 256 rows x 4 chunks
    const int b_row = tid >> 2;          // 0..63 base; 4 row-groups of 64
    const int b_c = tid & 3;
    auto issueB = [&](int gc) {
        const int nt = gc / NKT, kt = gc % NKT, s = gc % 3;
        const __nv_bfloat16* src = g_eyn + (size_t)nt * BN * DDIM + kt * BK;
        const uint32_t dst = sb + OFF_B + s * B_STAGE_B + b_c * 16;
#pragma unroll
        for (int r4 = 0; r4 < 4; r4++) {
            const int row = r4 * 64 + b_row;
            cpa16(dst + row * B_ROW_B, src + (size_t)row * DDIM + b_c * 8);
        }
    };
    issueB(0); cpa_commit();
    issueB(1); cpa_commit();

    // ldsm addressing
    const int lrow = lane & 15;
    const int koff = (lane >> 4) * 16;   // bytes
    const uint32_t aAddr0 = sb + OFF_A + (wm * 32 + lrow) * A_STRIDE_B + koff;
    const uint32_t bAddrBase = sb + OFF_B + (wn * 64 + lrow) * B_ROW_B + koff;

    float runmax[2][2];
#pragma unroll
    for (int i = 0; i < 2; i++)
#pragma unroll
        for (int j = 0; j < 2; j++) runmax[i][j] = -1e30f;

    int gc = 0;
    for (int nt = 0; nt < NNT; ++nt) {
        float acc[2][8][4];
#pragma unroll
        for (int mt = 0; mt < 2; mt++)
#pragma unroll
            for (int n8 = 0; n8 < 8; n8++)
#pragma unroll
                for (int r = 0; r < 4; r++) acc[mt][n8][r] = 0.f;

        for (int kt = 0; kt < NKT; ++kt, ++gc) {
            cpa_wait1();
            __syncthreads();
            if (gc + 2 < TOTAL_CH) issueB(gc + 2);
            cpa_commit();

            const uint32_t bStage = bAddrBase + (gc % 3) * B_STAGE_B;
#pragma unroll
            for (int kk = 0; kk < 2; ++kk) {
                uint32_t a[2][4], b[4][4];
#pragma unroll
                for (int mt = 0; mt < 2; mt++)
                    ldsm4(a[mt], aAddr0 + mt * 16 * A_STRIDE_B + kt * 64 + kk * 32);
#pragma unroll
                for (int n16 = 0; n16 < 4; n16++)
                    ldsm4(b[n16], bStage + n16 * 16 * B_ROW_B + kk * 32);
#pragma unroll
                for (int mt = 0; mt < 2; mt++)
#pragma unroll
                    for (int n8 = 0; n8 < 8; n8++) {
                        const int n16 = n8 >> 1, sub = n8 & 1;
                        mma16816(acc[mt][n8], a[mt], b[n16][sub], b[n16][sub + 2]);
                    }
            }
        }

#pragma unroll
        for (int mt = 0; mt < 2; mt++) {
            float m0 = runmax[mt][0], m1 = runmax[mt][1];
#pragma unroll
            for (int n8 = 0; n8 < 8; n8++) {
                m0 = fmaxf(m0, fmaxf(acc[mt][n8][0], acc[mt][n8][1]));
                m1 = fmaxf(m1, fmaxf(acc[mt][n8][2], acc[mt][n8][3]));
            }
            runmax[mt][0] = m0;
            runmax[mt][1] = m1;
        }
    }

    // cross-thread reduction
#pragma unroll
    for (int mt = 0; mt < 2; mt++) {
#pragma unroll
        for (int h = 0; h < 2; h++) {
            float m = runmax[mt][h];
            m = fmaxf(m, __shfl_xor_sync(0xffffffffu, m, 1));
            m = fmaxf(m, __shfl_xor_sync(0xffffffffu, m, 2));
            if (tig == 0)
                red[wn * BM + wm * 32 + mt * 16 + h * 8 + g] = m;
        }
    }
    __syncthreads();

    if (tid < BM) {
        float m = red[tid];
#pragma unroll
        for (int w = 1; w < 4; w++) m = fmaxf(m, red[w * BM + tid]);
        out[bm * BM + tid] = m;
    }
}

// ---------------------------------------------------------------------------
// launch
// ---------------------------------------------------------------------------
extern "C" void kernel_launch(void* const* d_in, const int* in_sizes, int n_in,
                              void* d_out, int out_size) {
    const float* ex = (const float*)d_in[0];
    const float* ey = (const float*)d_in[1];
    float* out = (float*)d_out;

    cudaFuncSetAttribute(chamfer_kernel, cudaFuncAttributeMaxDynamicSharedMemorySize,
                         SMEM_TOTAL);

    normalize_kernel<<<NROWS, 256>>>(ex, 0);
    normalize_kernel<<<NROWS, 256>>>(ey, 1);
    chamfer_kernel<<<NROWS / BM, 256, SMEM_TOTAL>>>(out);
}